// round 2
// baseline (speedup 1.0000x reference)
#include <cuda_runtime.h>
#include <math.h>

#define Nn     8192
#define Bb     4
#define Ee     262144
#define EMBED  64
#define HIDDEN 512
#define OUTD   64
#define DCAP   192

// Scratch (allocation-free rule: __device__ globals)
__device__ int   g_outdeg[Bb * Nn];
__device__ __align__(16) int g_cnt[Bb * Nn * 4];
__device__ float g_vec[5 * HIDDEN];              // v0 (deg), v1..v4 (per-perturb-slot)
__device__ float g_table[(DCAP + 1) * OUTD];     // out row per outdeg, cnt==0 case

// ---------------------------------------------------------------------------
__global__ void zero_kernel() {
    int i = blockIdx.x * blockDim.x + threadIdx.x;   // 163840 threads exactly
    if (i < Bb * Nn) g_outdeg[i] = 0;
    else             g_cnt[i - Bb * Nn] = 0;
}

// ---------------------------------------------------------------------------
__global__ void hist_kernel(const int* __restrict__ ei, const int* __restrict__ pert) {
    __shared__ int p[4];
    if (threadIdx.x < 4) p[threadIdx.x] = pert[threadIdx.x];
    __syncthreads();
    int idx = blockIdx.x * blockDim.x + threadIdx.x;
    if (idx >= Bb * Ee) return;
    int b = idx >> 18;            // Ee == 2^18
    int e = idx & (Ee - 1);
    const int* base = ei + (size_t)b * 2 * Ee;
    int src = base[e];
    int dst = base[Ee + e];
    atomicAdd(&g_outdeg[b * Nn + src], 1);
    int cb = (b * Nn + src) * 4;
    if (dst == p[0]) atomicAdd(&g_cnt[cb + 0], 1);
    if (dst == p[1]) atomicAdd(&g_cnt[cb + 1], 1);
    if (dst == p[2]) atomicAdd(&g_cnt[cb + 2], 1);
    if (dst == p[3]) atomicAdd(&g_cnt[cb + 3], 1);
}

// ---------------------------------------------------------------------------
// omega[n, j] = H[n, j/4]  (stack axis=-1 then reshape => each embed value
// repeated 4x consecutively). So the folded weight is
//   w1s[k,e] = sum_{m<4} w1[k, e*4 + m]
// v0[k] = sum_e w1s[k,e]*proj_b[e] ; vb[k] = sum_e w1s[k,e]*proj_w[e,b]
__global__ void vec_kernel(const float* __restrict__ w1,
                           const float* __restrict__ proj_w,
                           const float* __restrict__ proj_b) {
    int k = blockIdx.x * blockDim.x + threadIdx.x;
    if (k >= HIDDEN) return;
    float a0 = 0.f, a1 = 0.f, a2 = 0.f, a3 = 0.f, a4 = 0.f;
    const float* row = w1 + (size_t)k * (4 * EMBED);
    #pragma unroll 8
    for (int e = 0; e < EMBED; e++) {
        float4 w4 = *(const float4*)(row + e * 4);
        float s = w4.x + w4.y + w4.z + w4.w;
        a0 += s * proj_b[e];
        float4 pw = *(const float4*)(proj_w + e * 4);   // (EMBED,B) row-major, B=4
        a1 += s * pw.x; a2 += s * pw.y; a3 += s * pw.z; a4 += s * pw.w;
    }
    g_vec[k]              = a0;
    g_vec[HIDDEN + k]     = a1;
    g_vec[2 * HIDDEN + k] = a2;
    g_vec[3 * HIDDEN + k] = a3;
    g_vec[4 * HIDDEN + k] = a4;
}

// ---------------------------------------------------------------------------
// Full per-node pipeline: h = b1 + deg*v0 + sum cnt*vb ; LN ; exact GELU ; @ w2.T + b2
// Runs with exactly 64 threads per block.
__device__ __forceinline__ void node_pipeline(
    float deg, float c0, float c1, float c2, float c3,
    const float* __restrict__ b1, const float* __restrict__ ln_g,
    const float* __restrict__ ln_b, const float* __restrict__ w2,
    const float* __restrict__ b2, float* __restrict__ out) {

    __shared__ float sh[HIDDEN];
    __shared__ float red_s[2], red_q[2];
    int t = threadIdx.x;

    float ps = 0.f, pq = 0.f;
    #pragma unroll
    for (int i = 0; i < HIDDEN / 64; i++) {
        int k = t + i * 64;
        float h = b1[k] + deg * g_vec[k]
                + c0 * g_vec[HIDDEN + k]     + c1 * g_vec[2 * HIDDEN + k]
                + c2 * g_vec[3 * HIDDEN + k] + c3 * g_vec[4 * HIDDEN + k];
        sh[k] = h;
        ps += h; pq += h * h;
    }
    #pragma unroll
    for (int o = 16; o > 0; o >>= 1) {
        ps += __shfl_down_sync(0xffffffffu, ps, o);
        pq += __shfl_down_sync(0xffffffffu, pq, o);
    }
    if ((t & 31) == 0) { red_s[t >> 5] = ps; red_q[t >> 5] = pq; }
    __syncthreads();
    float S  = red_s[0] + red_s[1];
    float Q  = red_q[0] + red_q[1];
    float mu = S * (1.f / HIDDEN);
    float var = Q * (1.f / HIDDEN) - mu * mu;
    float inv = rsqrtf(var + 1e-5f);

    #pragma unroll
    for (int i = 0; i < HIDDEN / 64; i++) {
        int k = t + i * 64;
        float x = (sh[k] - mu) * inv * ln_g[k] + ln_b[k];
        sh[k] = 0.5f * x * (1.f + erff(x * 0.7071067811865476f));   // exact GELU
    }
    __syncthreads();

    float acc = b2[t];
    const float4* w2r = (const float4*)(w2 + (size_t)t * HIDDEN);
    const float4* shv = (const float4*)sh;
    #pragma unroll 8
    for (int i = 0; i < HIDDEN / 4; i++) {
        float4 w  = w2r[i];
        float4 h4 = shv[i];
        acc += h4.x * w.x + h4.y * w.y + h4.z * w.z + h4.w * w.w;
    }
    out[t] = acc;
}

// ---------------------------------------------------------------------------
__global__ void table_kernel(const float* __restrict__ b1, const float* __restrict__ ln_g,
                             const float* __restrict__ ln_b, const float* __restrict__ w2,
                             const float* __restrict__ b2) {
    node_pipeline((float)blockIdx.x, 0.f, 0.f, 0.f, 0.f,
                  b1, ln_g, ln_b, w2, b2, g_table + (size_t)blockIdx.x * OUTD);
}

__global__ void node_kernel(const float* __restrict__ b1, const float* __restrict__ ln_g,
                            const float* __restrict__ ln_b, const float* __restrict__ w2,
                            const float* __restrict__ b2, float* __restrict__ out) {
    int bn  = blockIdx.x;                 // b*N + n
    int deg = g_outdeg[bn];
    int4 c  = *(const int4*)(g_cnt + (size_t)bn * 4);
    float* o = out + (size_t)bn * OUTD;
    if (((c.x | c.y | c.z | c.w) == 0) && deg <= DCAP) {
        o[threadIdx.x] = g_table[deg * OUTD + threadIdx.x];
    } else {
        node_pipeline((float)deg, (float)c.x, (float)c.y, (float)c.z, (float)c.w,
                      b1, ln_g, ln_b, w2, b2, o);
    }
}

// ---------------------------------------------------------------------------
extern "C" void kernel_launch(void* const* d_in, const int* in_sizes, int n_in,
                              void* d_out, int out_size) {
    const int*   ei     = (const int*)  d_in[0];
    const int*   pert   = (const int*)  d_in[1];
    const float* proj_w = (const float*)d_in[2];
    const float* proj_b = (const float*)d_in[3];
    const float* w1     = (const float*)d_in[4];
    const float* b1     = (const float*)d_in[5];
    const float* ln_g   = (const float*)d_in[6];
    const float* ln_b   = (const float*)d_in[7];
    const float* w2     = (const float*)d_in[8];
    const float* b2     = (const float*)d_in[9];
    float* out = (float*)d_out;

    zero_kernel<<<640, 256>>>();                       // 163840 = Bb*Nn*5 threads
    hist_kernel<<<(Bb * Ee) / 256, 256>>>(ei, pert);
    vec_kernel<<<2, 256>>>(w1, proj_w, proj_b);
    table_kernel<<<DCAP + 1, 64>>>(b1, ln_g, ln_b, w2, b2);
    node_kernel<<<Bb * Nn, 64>>>(b1, ln_g, ln_b, w2, b2, out);
}

// round 3
// speedup vs baseline: 1.1037x; 1.1037x over previous
#include <cuda_runtime.h>
#include <math.h>

#define Nn     8192
#define Bb     4
#define Ee     262144
#define EMBED  64
#define HIDDEN 512
#define OUTD   64
#define DCAP   192

// Scratch (allocation-free rule: __device__ globals)
__device__ int   g_outdeg[Bb * Nn];
__device__ __align__(16) int g_cnt[Bb * Nn * 4];
__device__ float g_vec[5 * HIDDEN];              // v0 (deg), v1..v4 (per-perturb-slot)
__device__ float g_table[(DCAP + 1) * OUTD];     // out row per outdeg for cnt==0 nodes
__device__ int   g_queue[Bb * Nn];
__device__ int   g_qcnt;

// ---------------------------------------------------------------------------
// Fused: zero histograms/queue + compute folded weight vectors.
// omega[n, j] = H[n, j/4]  (stack axis=-1 then reshape => each embed value
// repeated 4x consecutively):  w1s[k,e] = sum_{m<4} w1[k, e*4 + m]
// v0[k] = w1s[k,:] . proj_b ; vb[k] = w1s[k,:] . proj_w[:,b]
__global__ void init_kernel(const float* __restrict__ w1,
                            const float* __restrict__ proj_w,
                            const float* __restrict__ proj_b) {
    int i = blockIdx.x * blockDim.x + threadIdx.x;
    if (i == 0) g_qcnt = 0;
    if (i < Bb * Nn) { g_outdeg[i] = 0; return; }
    if (i < 5 * Bb * Nn) { g_cnt[i - Bb * Nn] = 0; return; }
    int k = i - 5 * Bb * Nn;
    if (k >= HIDDEN) return;
    float a0 = 0.f, a1 = 0.f, a2 = 0.f, a3 = 0.f, a4 = 0.f;
    const float* row = w1 + (size_t)k * (4 * EMBED);
    #pragma unroll 8
    for (int e = 0; e < EMBED; e++) {
        float4 w4 = *(const float4*)(row + e * 4);
        float s = w4.x + w4.y + w4.z + w4.w;
        a0 += s * proj_b[e];
        float4 pw = *(const float4*)(proj_w + e * 4);   // (EMBED,B) row-major, B=4
        a1 += s * pw.x; a2 += s * pw.y; a3 += s * pw.z; a4 += s * pw.w;
    }
    g_vec[k]              = a0;
    g_vec[HIDDEN + k]     = a1;
    g_vec[2 * HIDDEN + k] = a2;
    g_vec[3 * HIDDEN + k] = a3;
    g_vec[4 * HIDDEN + k] = a4;
}

// ---------------------------------------------------------------------------
// 4 edges per thread, int4 loads.
__global__ void hist_kernel(const int* __restrict__ ei, const int* __restrict__ pert) {
    __shared__ int p[4];
    if (threadIdx.x < 4) p[threadIdx.x] = pert[threadIdx.x];
    __syncthreads();
    int idx = blockIdx.x * blockDim.x + threadIdx.x;      // Bb*Ee/4 threads
    int b  = idx >> 16;                                   // (idx*4) >> 18
    int e4 = (idx & ((Ee / 4) - 1)) * 4;
    const int* base = ei + (size_t)b * 2 * Ee;
    int4 src = *(const int4*)(base + e4);
    int4 dst = *(const int4*)(base + Ee + e4);
    int gb = b * Nn;
    #pragma unroll
    for (int j = 0; j < 4; j++) {
        int s = (j == 0) ? src.x : (j == 1) ? src.y : (j == 2) ? src.z : src.w;
        int d = (j == 0) ? dst.x : (j == 1) ? dst.y : (j == 2) ? dst.z : dst.w;
        atomicAdd(&g_outdeg[gb + s], 1);
        int cb = (gb + s) * 4;
        if (d == p[0]) atomicAdd(&g_cnt[cb + 0], 1);
        if (d == p[1]) atomicAdd(&g_cnt[cb + 1], 1);
        if (d == p[2]) atomicAdd(&g_cnt[cb + 2], 1);
        if (d == p[3]) atomicAdd(&g_cnt[cb + 3], 1);
    }
}

// ---------------------------------------------------------------------------
// 512-thread pipeline: h = b1 + deg*v0 + sum cnt*vb ; LN ; exact GELU ; @ w2.T + b2
__device__ __forceinline__ void node_pipeline512(
    float deg, float c0, float c1, float c2, float c3,
    const float* __restrict__ b1, const float* __restrict__ ln_g,
    const float* __restrict__ ln_b, const float* __restrict__ w2,
    const float* __restrict__ b2, float* __restrict__ out) {

    __shared__ float sh[HIDDEN];
    __shared__ float rs[16], rq[16];
    __shared__ float s_mu, s_inv;
    int t = threadIdx.x;

    float h = b1[t] + deg * g_vec[t]
            + c0 * g_vec[HIDDEN + t]     + c1 * g_vec[2 * HIDDEN + t]
            + c2 * g_vec[3 * HIDDEN + t] + c3 * g_vec[4 * HIDDEN + t];

    float ps = h, pq = h * h;
    #pragma unroll
    for (int o = 16; o > 0; o >>= 1) {
        ps += __shfl_down_sync(0xffffffffu, ps, o);
        pq += __shfl_down_sync(0xffffffffu, pq, o);
    }
    if ((t & 31) == 0) { rs[t >> 5] = ps; rq[t >> 5] = pq; }
    __syncthreads();
    if (t < 32) {
        float a = (t < 16) ? rs[t] : 0.f;
        float q = (t < 16) ? rq[t] : 0.f;
        #pragma unroll
        for (int o = 8; o > 0; o >>= 1) {
            a += __shfl_down_sync(0xffffffffu, a, o);
            q += __shfl_down_sync(0xffffffffu, q, o);
        }
        if (t == 0) {
            float mu  = a * (1.f / HIDDEN);
            float var = q * (1.f / HIDDEN) - mu * mu;
            s_mu  = mu;
            s_inv = rsqrtf(var + 1e-5f);
        }
    }
    __syncthreads();

    float x = (h - s_mu) * s_inv * ln_g[t] + ln_b[t];
    sh[t] = 0.5f * x * (1.f + erff(x * 0.7071067811865476f));   // exact GELU
    __syncthreads();

    // GEMV: thread (o=t>>3, part=t&7) sums k = part + 8j  (coalesced w2 sectors)
    int o = t >> 3, part = t & 7;
    const float* w2r = w2 + (size_t)o * HIDDEN + part;
    float acc = 0.f;
    #pragma unroll 16
    for (int j = 0; j < HIDDEN / 8; j++)
        acc += sh[part + 8 * j] * w2r[8 * j];
    #pragma unroll
    for (int off = 4; off > 0; off >>= 1)
        acc += __shfl_down_sync(0xffffffffu, acc, off);
    if (part == 0) out[o] = acc + b2[o];
}

// ---------------------------------------------------------------------------
__global__ void table_kernel(const float* __restrict__ b1, const float* __restrict__ ln_g,
                             const float* __restrict__ ln_b, const float* __restrict__ w2,
                             const float* __restrict__ b2) {
    node_pipeline512((float)blockIdx.x, 0.f, 0.f, 0.f, 0.f,
                     b1, ln_g, ln_b, w2, b2, g_table + (size_t)blockIdx.x * OUTD);
}

// ---------------------------------------------------------------------------
// Warp-per-node fast path; slow nodes queued for fixup.
__global__ void node_kernel(float* __restrict__ out) {
    int warp = (blockIdx.x * blockDim.x + threadIdx.x) >> 5;   // Bb*Nn warps
    int lane = threadIdx.x & 31;
    int bn = warp;
    int deg = __ldg(&g_outdeg[bn]);                 // broadcast (uniform per warp)
    int4 c  = *(const int4*)(g_cnt + (size_t)bn * 4);
    if (((c.x | c.y | c.z | c.w) == 0) && deg <= DCAP) {
        float2 v = *(const float2*)(g_table + deg * OUTD + lane * 2);
        *(float2*)(out + (size_t)bn * OUTD + lane * 2) = v;
    } else if (lane == 0) {
        int q = atomicAdd(&g_qcnt, 1);
        g_queue[q] = bn;
    }
}

__global__ void fixup_kernel(const float* __restrict__ b1, const float* __restrict__ ln_g,
                             const float* __restrict__ ln_b, const float* __restrict__ w2,
                             const float* __restrict__ b2, float* __restrict__ out) {
    int qn = g_qcnt;
    for (int q = blockIdx.x; q < qn; q += gridDim.x) {
        int bn  = g_queue[q];
        int deg = g_outdeg[bn];
        int4 c  = *(const int4*)(g_cnt + (size_t)bn * 4);
        node_pipeline512((float)deg, (float)c.x, (float)c.y, (float)c.z, (float)c.w,
                         b1, ln_g, ln_b, w2, b2, out + (size_t)bn * OUTD);
        __syncthreads();
    }
}

// ---------------------------------------------------------------------------
extern "C" void kernel_launch(void* const* d_in, const int* in_sizes, int n_in,
                              void* d_out, int out_size) {
    const int*   ei     = (const int*)  d_in[0];
    const int*   pert   = (const int*)  d_in[1];
    const float* proj_w = (const float*)d_in[2];
    const float* proj_b = (const float*)d_in[3];
    const float* w1     = (const float*)d_in[4];
    const float* b1     = (const float*)d_in[5];
    const float* ln_g   = (const float*)d_in[6];
    const float* ln_b   = (const float*)d_in[7];
    const float* w2     = (const float*)d_in[8];
    const float* b2     = (const float*)d_in[9];
    float* out = (float*)d_out;

    init_kernel<<<(5 * Bb * Nn + HIDDEN + 255) / 256, 256>>>(w1, proj_w, proj_b);
    hist_kernel<<<(Bb * Ee / 4) / 256, 256>>>(ei, pert);
    table_kernel<<<DCAP + 1, 512>>>(b1, ln_g, ln_b, w2, b2);
    node_kernel<<<(Bb * Nn * 32) / 256, 256>>>(out);
    fixup_kernel<<<64, 512>>>(b1, ln_g, ln_b, w2, b2, out);
}